// round 2
// baseline (speedup 1.0000x reference)
#include <cuda_runtime.h>
#include <cstdint>

#define NN 16384
#define HH 2048
#define KN 25
#define CHUNK 128
#define NCHUNK (HH / CHUNK)
#define RPW 2
#define NWARPS 8
#define RPB (RPW * NWARPS)        // 16 rows per block
#define NTHREADS (NWARPS * 32)    // 256
#define CHUNK_BYTES (KN * CHUNK * 4)  // 12800

__device__ __forceinline__ uint32_t smem_u32(const void* p) {
    return (uint32_t)__cvta_generic_to_shared(p);
}

__device__ __forceinline__ void bulk_g2s(uint32_t dst, const void* src,
                                         uint32_t bytes, uint32_t mbar) {
    asm volatile(
        "cp.async.bulk.shared::cta.global.mbarrier::complete_tx::bytes [%0], [%1], %2, [%3];"
        :: "r"(dst), "l"(src), "r"(bytes), "r"(mbar) : "memory");
}

__device__ __forceinline__ void mbar_init(uint32_t mbar, uint32_t count) {
    asm volatile("mbarrier.init.shared.b64 [%0], %1;" :: "r"(mbar), "r"(count) : "memory");
}

__device__ __forceinline__ void mbar_expect_tx(uint32_t mbar, uint32_t bytes) {
    asm volatile("mbarrier.arrive.expect_tx.shared.b64 _, [%0], %1;"
                 :: "r"(mbar), "r"(bytes) : "memory");
}

__device__ __forceinline__ void mbar_wait(uint32_t mbar, uint32_t parity) {
    uint32_t done;
    asm volatile(
        "{\n\t.reg .pred p;\n\t"
        "mbarrier.try_wait.parity.acquire.cta.shared::cta.b64 p, [%1], %2;\n\t"
        "selp.b32 %0, 1, 0, p;\n\t}"
        : "=r"(done) : "r"(mbar), "r"(parity) : "memory");
    if (!done) {
        asm volatile(
            "{\n\t.reg .pred P1;\n\t"
            "WAIT_LOOP_%=:\n\t"
            "mbarrier.try_wait.parity.acquire.cta.shared::cta.b64 P1, [%0], %1, 0x989680;\n\t"
            "@P1 bra.uni WAIT_DONE_%=;\n\t"
            "bra.uni WAIT_LOOP_%=;\n\t"
            "WAIT_DONE_%=:\n\t}"
            :: "r"(mbar), "r"(parity) : "memory");
    }
}

__global__ __launch_bounds__(NTHREADS, 2)
void nce_kernel(const float* __restrict__ input,
                const float* __restrict__ weight,
                const float* __restrict__ bias,
                const float* __restrict__ unig,
                const int* __restrict__ target,
                const int* __restrict__ noise,
                float* __restrict__ out)
{
    __shared__ __align__(1024) float sw[2][KN][CHUNK];   // 25.6 KB double buffer
    __shared__ __align__(8) unsigned long long mbar_store[2];
    __shared__ int s_noise[KN];
    __shared__ float s_nb[KN], s_nu[KN];

    const int tid  = threadIdx.x;
    const int lane = tid & 31;
    const int wid  = tid >> 5;
    const int rb   = blockIdx.x * RPB;
    const int row0 = rb + wid * RPW;

    const uint32_t mb0 = smem_u32(&mbar_store[0]);
    const uint32_t mb1 = smem_u32(&mbar_store[1]);
    const uint32_t sw0 = smem_u32(&sw[0][0][0]);
    const uint32_t sw1 = smem_u32(&sw[1][0][0]);

    if (tid < KN) {
        int nk = noise[tid];
        s_noise[tid] = nk;
        s_nb[tid] = bias[nk];
        s_nu[tid] = unig[nk];
    }
    if (tid == 0) {
        mbar_init(mb0, 1);
        mbar_init(mb1, 1);
    }
    asm volatile("fence.proxy.async.shared::cta;" ::: "memory");
    __syncthreads();

    // ---- early independent outputs: pnn (broadcast) and pnt (gathered unigram) ----
    {
        const size_t pnn_base = (size_t)2 * NN + (size_t)NN * KN + (size_t)rb * KN;
        #pragma unroll 1
        for (int i = tid; i < RPB * KN; i += NTHREADS)
            out[pnn_base + i] = s_nu[i % KN];
        if (tid < RPB) {
            int n = rb + tid;
            out[NN + n] = unig[target[n]];
        }
    }

    // ---- prolog: bulk-copy chunk 0 of the noise tile ----
    if (tid == 0) {
        mbar_expect_tx(mb0, CHUNK_BYTES);
        #pragma unroll 1
        for (int k = 0; k < KN; k++) {
            const float* g = weight + (size_t)s_noise[k] * HH;  // chunk 0
            bulk_g2s(sw0 + (uint32_t)(k * CHUNK * 4), g, CHUNK * 4, mb0);
        }
    }

    int tgt[RPW];
    const float4* xp[RPW];
    const float4* wtp[RPW];
    #pragma unroll
    for (int r = 0; r < RPW; r++) {
        int n = row0 + r;
        tgt[r] = target[n];
        xp[r]  = reinterpret_cast<const float4*>(input)  + (size_t)n * (HH / 4);
        wtp[r] = reinterpret_cast<const float4*>(weight) + (size_t)tgt[r] * (HH / 4);
    }

    float acc[RPW][KN];
    float acct[RPW];
    #pragma unroll
    for (int r = 0; r < RPW; r++) {
        acct[r] = 0.f;
        #pragma unroll
        for (int k = 0; k < KN; k++) acc[r][k] = 0.f;
    }

    // register prefetch of input + target-weight for chunk 0 (overlaps bulk copy)
    float4 x[RPW], wt[RPW];
    #pragma unroll
    for (int r = 0; r < RPW; r++) { x[r] = xp[r][lane]; wt[r] = wtp[r][lane]; }

    #pragma unroll 1
    for (int c = 0; c < NCHUNK; c++) {
        const int buf = c & 1;
        const uint32_t mb_cur = buf ? mb1 : mb0;

        // issue bulk copy for chunk c+1 into the other buffer (safe: everyone
        // finished reading it at the end-of-iteration barrier of c-1)
        if (c + 1 < NCHUNK && tid == 0) {
            const uint32_t mb_nxt = buf ? mb0 : mb1;
            const uint32_t sw_nxt = buf ? sw0 : sw1;
            mbar_expect_tx(mb_nxt, CHUNK_BYTES);
            #pragma unroll 1
            for (int k = 0; k < KN; k++) {
                const float* g = weight + (size_t)s_noise[k] * HH + (c + 1) * CHUNK;
                bulk_g2s(sw_nxt + (uint32_t)(k * CHUNK * 4), g, CHUNK * 4, mb_nxt);
            }
        }

        // wait for chunk c's noise tile
        mbar_wait(mb_cur, (c >> 1) & 1);

        // register prefetch x / target-weight for chunk c+1
        float4 xn[RPW], wtn[RPW];
        if (c + 1 < NCHUNK) {
            #pragma unroll
            for (int r = 0; r < RPW; r++) {
                int idx = (c + 1) * (CHUNK / 4) + lane;
                xn[r]  = xp[r][idx];
                wtn[r] = wtp[r][idx];
            }
        }

        const float4* wrow = reinterpret_cast<const float4*>(&sw[buf][0][0]) + lane;
        #pragma unroll
        for (int k = 0; k < KN; k++) {
            float4 w = wrow[k * (CHUNK / 4)];
            #pragma unroll
            for (int r = 0; r < RPW; r++) {
                float a = acc[r][k];
                a = fmaf(x[r].x, w.x, a);
                a = fmaf(x[r].y, w.y, a);
                a = fmaf(x[r].z, w.z, a);
                a = fmaf(x[r].w, w.w, a);
                acc[r][k] = a;
            }
        }
        #pragma unroll
        for (int r = 0; r < RPW; r++) {
            float a = acct[r];
            a = fmaf(x[r].x, wt[r].x, a);
            a = fmaf(x[r].y, wt[r].y, a);
            a = fmaf(x[r].z, wt[r].z, a);
            a = fmaf(x[r].w, wt[r].w, a);
            acct[r] = a;
        }

        if (c + 1 < NCHUNK) {
            #pragma unroll
            for (int r = 0; r < RPW; r++) { x[r] = xn[r]; wt[r] = wtn[r]; }
        }

        __syncthreads();   // all warps done reading buf before it is refilled
    }

    // ---- warp butterfly reduction over lanes (each lane held a disjoint H slice) ----
    #pragma unroll
    for (int off = 16; off > 0; off >>= 1) {
        #pragma unroll
        for (int r = 0; r < RPW; r++) {
            acct[r] += __shfl_xor_sync(0xffffffffu, acct[r], off);
            #pragma unroll
            for (int k = 0; k < KN; k++)
                acc[r][k] += __shfl_xor_sync(0xffffffffu, acc[r][k], off);
        }
    }

    // ---- outputs: pmn via predicated constant-index stores, pmt ----
    #pragma unroll
    for (int r = 0; r < RPW; r++) {
        const int n = row0 + r;
        float* pmn_row = out + (size_t)2 * NN + (size_t)n * KN;
        #pragma unroll
        for (int k = 0; k < KN; k++) {
            if (lane == k) pmn_row[k] = expf(acc[r][k] + s_nb[k]);
        }
        if (lane == KN) {
            out[n] = expf(acct[r] + bias[tgt[r]]);
        }
    }
}

extern "C" void kernel_launch(void* const* d_in, const int* in_sizes, int n_in,
                              void* d_out, int out_size) {
    const float* input  = (const float*)d_in[0];
    const float* weight = (const float*)d_in[1];
    const float* bias   = (const float*)d_in[2];
    const float* unig   = (const float*)d_in[3];
    const int*   target = (const int*)d_in[4];
    const int*   noise  = (const int*)d_in[5];
    float* out = (float*)d_out;

    nce_kernel<<<NN / RPB, NTHREADS>>>(input, weight, bias, unig, target, noise, out);
}